// round 14
// baseline (speedup 1.0000x reference)
#include <cuda_runtime.h>
#include <cuda_bf16.h>
#include <math.h>

// Problem constants
#define B    64
#define C    256
#define S    3136          // 56*56
#define S4   784           // S/4 (float4 units)
#define HID  196
#define HID4 49            // HID/4
#define KSEL 1568          // rank of first KEPT element (0-indexed kth smallest)
#define QS   16            // pool c-split

// K-split for GEMM1
#define KC   49
#define KCH  64            // 3136/49

// Scratch (device globals: no allocation allowed)
__device__ float g_Yp[QS][B * S];       // pooled partial sums (16 c-slices)
__device__ float g_Hpart[KC * B * HID]; // GEMM1 partials        [49][64*196]
__device__ float g_H[B * HID];          // relu(hidden)          [64,196]
__device__ float g_S[B * S];            // sigmoid outputs       [64,3136]
__device__ float g_M[B * S];            // masked row            [64,3136]
__device__ float g_scratch[128 * 8];    // prefetch sink (never read)

// ---------------------------------------------------------------------------
// K1: channel-mean pool (partial, c-split x16) FUSED with W1/W2 L2-prefetch.
// Blocks 0..127:    warm W1+W2 (4.9MB) into L2 via __ldcg.
// Blocks 128..3263: 3136 balanced pool blocks; each thread sums one float4
//   column over 16 channels (__ldcs evict-first) into g_Yp[slice].
// Finer blocks -> better last-wave balance on the BW-bound stream.
// grid 3264, block 256
// ---------------------------------------------------------------------------
__global__ void k_pool(const float* __restrict__ x,
                       const float* __restrict__ W1,
                       const float* __restrict__ W2) {
    int blk = blockIdx.x;
    if (blk < 128) {
        const int NF4 = (S * HID) / 4;               // 153664 float4 per matrix
        int t = blk * 256 + threadIdx.x;             // 0..32767
        float s = 0.f;
        const float4* w1 = reinterpret_cast<const float4*>(W1);
        const float4* w2 = reinterpret_cast<const float4*>(W2);
        for (int i = t; i < NF4; i += 128 * 256) {
            float4 a = __ldcg(w1 + i);
            float4 b4 = __ldcg(w2 + i);
            s += a.x + a.y + a.z + a.w + b4.x + b4.y + b4.z + b4.w;
        }
#pragma unroll
        for (int off = 16; off > 0; off >>= 1)
            s += __shfl_down_sync(0xFFFFFFFFu, s, off);
        if ((threadIdx.x & 31) == 0)
            g_scratch[blk * 8 + (threadIdx.x >> 5)] = s;
    } else {
        int id = (blk - 128) * 256 + threadIdx.x;    // 0..802815
        int q   = id / (B * S4);                     // c-slice 0..15
        int id2 = id - q * (B * S4);                 // 0..50175
        int b = id2 / S4;
        int f = id2 - b * S4;                        // float4 column index
        const float4* xp = reinterpret_cast<const float4*>(x)
                         + (size_t)b * C * S4 + (size_t)q * 16 * S4 + f;
        float sx = 0.f, sy = 0.f, sz = 0.f, sw = 0.f;
#pragma unroll
        for (int c = 0; c < 16; c++) {
            float4 v = __ldcs(xp + (size_t)c * S4);
            sx += v.x; sy += v.y; sz += v.z; sw += v.w;
        }
        float4 o; o.x = sx; o.y = sy; o.z = sz; o.w = sw;
        reinterpret_cast<float4*>(g_Yp[q])[(size_t)b * S4 + f] = o;
    }
}

// ---------------------------------------------------------------------------
// K2: GEMM1 partials, 2o x 4b register tile (proven R9/R13 config) with PDL:
// W1 smem fill (independent) before cudaGridDependencySynchronize();
// g_Yp-dependent fill (16 partial slices) after.
// grid (49 kc, 7 o-tiles), block 256.
// ---------------------------------------------------------------------------
__global__ void k_gemm1(const float* __restrict__ W1) {
    __shared__ __align__(16) float sYT[KCH * 68];  // [j][b] (17.4KB)
    __shared__ __align__(8)  float sW[KCH * 28];   // [j][o_local] (7.2KB)
    int kc = blockIdx.x;
    int o0 = blockIdx.y * 28;
    int t = threadIdx.x;
    const float inv = 1.0f / 256.0f;

    // ---- independent preamble: W1 tile -> smem (overlaps pool tail) ----
    const float4* w4 = reinterpret_cast<const float4*>(W1);
    for (int idx = t; idx < 28 * 16; idx += 256) {
        int o = idx >> 4, jq = idx & 15;
        float4 w = w4[(size_t)(o0 + o) * S4 + kc * 16 + jq];
        sW[(jq * 4 + 0) * 28 + o] = w.x;
        sW[(jq * 4 + 1) * 28 + o] = w.y;
        sW[(jq * 4 + 2) * 28 + o] = w.z;
        sW[(jq * 4 + 3) * 28 + o] = w.w;
    }

    cudaGridDependencySynchronize();   // wait for k_pool's g_Yp writes

    for (int idx = t; idx < B * 16; idx += 256) {
        int b2 = idx >> 4, jq = idx & 15;
        int gi = b2 * S4 + kc * 16 + jq;
        float ax = 0.f, ay = 0.f, az = 0.f, aw = 0.f;
#pragma unroll
        for (int q = 0; q < QS; q++) {
            float4 v = reinterpret_cast<const float4*>(g_Yp[q])[gi];
            ax += v.x; ay += v.y; az += v.z; aw += v.w;
        }
        sYT[(jq * 4 + 0) * 68 + b2] = ax * inv;
        sYT[(jq * 4 + 1) * 68 + b2] = ay * inv;
        sYT[(jq * 4 + 2) * 68 + b2] = az * inv;
        sYT[(jq * 4 + 3) * 68 + b2] = aw * inv;
    }
    __syncthreads();

    if (t >= 224) return;
    int og = t % 14;                     // 2 o's: og*2, og*2+1
    int bg = t / 14;                     // 0..15 -> 4 b's: bg*4..+3
    float a00 = 0.f, a01 = 0.f, a02 = 0.f, a03 = 0.f;
    float a10 = 0.f, a11 = 0.f, a12 = 0.f, a13 = 0.f;
#pragma unroll 4
    for (int j = 0; j < KCH; j++) {
        float2 w = *reinterpret_cast<const float2*>(&sW[j * 28 + og * 2]);
        float4 y = *reinterpret_cast<const float4*>(&sYT[j * 68 + bg * 4]);
        a00 = fmaf(w.x, y.x, a00); a01 = fmaf(w.x, y.y, a01);
        a02 = fmaf(w.x, y.z, a02); a03 = fmaf(w.x, y.w, a03);
        a10 = fmaf(w.y, y.x, a10); a11 = fmaf(w.y, y.y, a11);
        a12 = fmaf(w.y, y.z, a12); a13 = fmaf(w.y, y.w, a13);
    }
    int ob = o0 + og * 2;
    int base = kc * (B * HID) + (bg * 4) * HID + ob;
    g_Hpart[base + 0 * HID + 0] = a00; g_Hpart[base + 0 * HID + 1] = a10;
    g_Hpart[base + 1 * HID + 0] = a01; g_Hpart[base + 1 * HID + 1] = a11;
    g_Hpart[base + 2 * HID + 0] = a02; g_Hpart[base + 2 * HID + 1] = a12;
    g_Hpart[base + 3 * HID + 0] = a03; g_Hpart[base + 3 * HID + 1] = a13;
}

// ---------------------------------------------------------------------------
// K3: reduce 49 partials + ReLU.  2 threads per output, shuffle combine.
// grid 98, block 256.  (proven)  PDL: sync at top.
// ---------------------------------------------------------------------------
__global__ void k_redrelu() {
    cudaGridDependencySynchronize();
    int tid = blockIdx.x * 256 + threadIdx.x;
    int g   = tid >> 1;                  // output index 0..12543
    int sub = tid & 1;
    float s = 0.f;
    for (int i = sub; i < KC; i += 2)
        s += g_Hpart[i * (B * HID) + g];
    s += __shfl_xor_sync(0xFFFFFFFFu, s, 1);
    if (sub == 0)
        g_H[g] = s > 0.f ? s : 0.f;
}

// ---------------------------------------------------------------------------
// K4: GEMM2 + sigmoid, 2n x 2b register tile (proven R9/R13 config) with PDL.
// grid (98, 2), block 256, 50KB dynamic smem.
// ---------------------------------------------------------------------------
__global__ void k_gemm2(const float* __restrict__ W2) {
    extern __shared__ float dyn[];
    float* sW2 = dyn;                 // [j][n_local] pitch 32
    float* sHT = dyn + HID * 32;      // [j][b_local] pitch 32
    int n0 = blockIdx.x * 32;
    int b0 = blockIdx.y * 32;
    int t = threadIdx.x;

    const float4* w4 = reinterpret_cast<const float4*>(W2);
    for (int idx = t; idx < 32 * HID4; idx += 256) {
        int nl = idx / HID4, jq = idx - nl * HID4;
        float4 w = w4[(size_t)(n0 + nl) * HID4 + jq];
        sW2[(jq * 4 + 0) * 32 + nl] = w.x;
        sW2[(jq * 4 + 1) * 32 + nl] = w.y;
        sW2[(jq * 4 + 2) * 32 + nl] = w.z;
        sW2[(jq * 4 + 3) * 32 + nl] = w.w;
    }

    cudaGridDependencySynchronize();   // wait for k_redrelu's g_H writes

    const float4* h4 = reinterpret_cast<const float4*>(g_H);
    for (int idx = t; idx < 32 * HID4; idx += 256) {
        int b2 = idx / HID4, jq = idx - b2 * HID4;
        float4 h = h4[(size_t)(b0 + b2) * HID4 + jq];
        sHT[(jq * 4 + 0) * 32 + b2] = h.x;
        sHT[(jq * 4 + 1) * 32 + b2] = h.y;
        sHT[(jq * 4 + 2) * 32 + b2] = h.z;
        sHT[(jq * 4 + 3) * 32 + b2] = h.w;
    }
    __syncthreads();

    int ng = t & 15;                             // 2 n's
    int bg = t >> 4;                             // 2 b's
    float a00 = 0.f, a01 = 0.f, a10 = 0.f, a11 = 0.f;
#pragma unroll 4
    for (int j = 0; j < HID; j++) {
        float2 w = *reinterpret_cast<const float2*>(&sW2[j * 32 + ng * 2]);
        float2 h = *reinterpret_cast<const float2*>(&sHT[j * 32 + bg * 2]);
        a00 = fmaf(h.x, w.x, a00); a01 = fmaf(h.x, w.y, a01);
        a10 = fmaf(h.y, w.x, a10); a11 = fmaf(h.y, w.y, a11);
    }
    int b = b0 + bg * 2;
    int n = n0 + ng * 2;
    g_S[(size_t)(b + 0) * S + n + 0] = 1.0f / (1.0f + expf(-a00));
    g_S[(size_t)(b + 0) * S + n + 1] = 1.0f / (1.0f + expf(-a01));
    g_S[(size_t)(b + 1) * S + n + 0] = 1.0f / (1.0f + expf(-a10));
    g_S[(size_t)(b + 1) * S + n + 1] = 1.0f / (1.0f + expf(-a11));
}

// ---------------------------------------------------------------------------
// Device helper: exact rank-1568 selection + masking for one row (proven
// R11/R13 logic, 512 threads, shared buffers passed in).
// ---------------------------------------------------------------------------
__device__ __forceinline__ void select_row(int b, float* sv, unsigned* hist,
                                           unsigned* wsum, unsigned* shp) {
    int t = threadIdx.x;
    int lane = t & 31, wid = t >> 5;

    for (int i = t; i < S; i += 512) sv[i] = g_S[b * S + i];
    if (t == 0) { shp[0] = 0u; shp[1] = KSEL; }
    __syncthreads();

    for (int shift = 24; shift >= 0; shift -= 8) {
        if (t < 256) hist[t] = 0u;
        __syncthreads();
        unsigned pref = shp[0];
        unsigned r    = shp[1];
        unsigned hm   = (shift == 24) ? 0u : (0xFFFFFFFFu << (shift + 8));
        for (int i = t; i < S; i += 512) {
            unsigned u = __float_as_uint(sv[i]);
            if ((u & hm) == pref) atomicAdd(&hist[(u >> shift) & 255], 1u);
        }
        __syncthreads();
        unsigned v = (t < 256) ? hist[t] : 0u;
        unsigned x = v;
#pragma unroll
        for (int off = 1; off < 32; off <<= 1) {
            unsigned y = __shfl_up_sync(0xFFFFFFFFu, x, off);
            if (lane >= off) x += y;
        }
        if (lane == 31) wsum[wid] = x;
        __syncthreads();
        if (t < 16) {
            unsigned s = wsum[t];
#pragma unroll
            for (int off = 1; off < 16; off <<= 1) {
                unsigned y = __shfl_up_sync(0xFFFFu, s, off);
                if (t >= off) s += y;
            }
            wsum[t] = s;
        }
        __syncthreads();
        unsigned incl = x + (wid ? wsum[wid - 1] : 0u);
        unsigned excl = incl - v;
        if (v > 0u && r >= excl && r < incl) {   // exactly one thread (t<256)
            shp[0] = pref | ((unsigned)t << shift);
            shp[1] = r - excl;
        }
        __syncthreads();
    }
    unsigned T    = shp[0];
    unsigned rfin = shp[1];

    int lo = (t * S) >> 9;
    int hi = ((t + 1) * S) >> 9;
    unsigned cnt = 0;
    for (int i = lo; i < hi; i++)
        cnt += (__float_as_uint(sv[i]) == T) ? 1u : 0u;
    unsigned x = cnt;
#pragma unroll
    for (int off = 1; off < 32; off <<= 1) {
        unsigned y = __shfl_up_sync(0xFFFFFFFFu, x, off);
        if (lane >= off) x += y;
    }
    if (lane == 31) wsum[wid] = x;
    __syncthreads();
    if (t < 16) {
        unsigned s = wsum[t];
#pragma unroll
        for (int off = 1; off < 16; off <<= 1) {
            unsigned y = __shfl_up_sync(0xFFFFu, s, off);
            if (t >= off) s += y;
        }
        wsum[t] = s;
    }
    __syncthreads();
    unsigned e = x - cnt + (wid ? wsum[wid - 1] : 0u);
    for (int i = lo; i < hi; i++) {
        unsigned u = __float_as_uint(sv[i]);
        float val = sv[i];
        if (u < T) val = 0.f;
        else if (u == T) { if (e < rfin) val = 0.f; e++; }
        g_M[b * S + i] = val;
    }
}

#define SEL_SMEM ((S + 256 + 16 + 2) * sizeof(float))

// ---------------------------------------------------------------------------
// K5: select for batch half 1 (b 0..31).  grid 32, block 512.  PDL sync.
// ---------------------------------------------------------------------------
__global__ void k_sel1() {
    extern __shared__ float dynf[];
    float* sv = dynf;
    unsigned* hist = reinterpret_cast<unsigned*>(dynf + S);
    unsigned* wsum = hist + 256;
    unsigned* shp  = wsum + 16;
    cudaGridDependencySynchronize();           // wait for k_gemm2's g_S
    select_row(blockIdx.x, sv, hist, wsum, shp);
}

// ---------------------------------------------------------------------------
// K6: select for half 2 (b 32..63, blocks 0..31) FUSED with broadcast of
// half 1 (blocks 32..423: 392 streamer blocks x 512 thr, 32 stores each —
// g_M rows 0..31 were finished by K5; PDL sync covers that).
// grid 424, block 512.
// ---------------------------------------------------------------------------
__global__ void k_sel2_bcast1(float* __restrict__ out) {
    extern __shared__ float dynf[];
    cudaGridDependencySynchronize();           // wait for k_sel1 (=> gemm2 too)
    int blk = blockIdx.x;
    if (blk < 32) {
        float* sv = dynf;
        unsigned* hist = reinterpret_cast<unsigned*>(dynf + S);
        unsigned* wsum = hist + 256;
        unsigned* shp  = wsum + 16;
        select_row(32 + blk, sv, hist, wsum, shp);
    } else {
        int id = (blk - 32) * 512 + threadIdx.x;   // 0..200703
        int f  = id % S4;
        int bc = id / S4;                          // 0..255 = b*8+cg
        int cg = bc & 7;
        int b  = bc >> 3;                          // 0..31
        float4 v = __ldcg(reinterpret_cast<const float4*>(g_M) + (size_t)b * S4 + f);
        float4* op = reinterpret_cast<float4*>(out)
                   + (size_t)(b * C + cg * 32) * S4 + f;
#pragma unroll 8
        for (int c = 0; c < 32; c++)
            __stcs(op + (size_t)c * S4, v);
    }
}

// ---------------------------------------------------------------------------
// K7: broadcast half 2 (b 32..63), c-split x16 for finer wave balance:
// grid 1568, block 256, 16 stores per thread.
// ---------------------------------------------------------------------------
__global__ void k_bcast2(float* __restrict__ out) {
    cudaGridDependencySynchronize();           // wait for k_sel2's g_M
    int id = blockIdx.x * 256 + threadIdx.x;     // 0..401407
    int f  = id % S4;
    int bc = id / S4;                            // 0..511 = b2*16+cg
    int cg = bc & 15;
    int b  = 32 + (bc >> 4);                     // 32..63
    float4 v = __ldcg(reinterpret_cast<const float4*>(g_M) + (size_t)b * S4 + f);
    float4* op = reinterpret_cast<float4*>(out)
               + (size_t)(b * C + cg * 16) * S4 + f;
#pragma unroll 8
    for (int c = 0; c < 16; c++)
        __stcs(op + (size_t)c * S4, v);
}

// ---------------------------------------------------------------------------
// Helper: launch with programmatic stream serialization (PDL)
// ---------------------------------------------------------------------------
template <typename... Args>
static void launch_pdl(void (*kern)(Args...), dim3 grid, dim3 block,
                       size_t smem, Args... args) {
    cudaLaunchConfig_t cfg = {};
    cfg.gridDim = grid;
    cfg.blockDim = block;
    cfg.dynamicSmemBytes = smem;
    cfg.stream = 0;
    cudaLaunchAttribute attr[1];
    attr[0].id = cudaLaunchAttributeProgrammaticStreamSerialization;
    attr[0].val.programmaticStreamSerializationAllowed = 1;
    cfg.attrs = attr;
    cfg.numAttrs = 1;
    cudaLaunchKernelEx(&cfg, kern, args...);
}

// ---------------------------------------------------------------------------
extern "C" void kernel_launch(void* const* d_in, const int* in_sizes, int n_in,
                              void* d_out, int out_size) {
    const float* x  = (const float*)d_in[0];
    const float* W1 = (const float*)d_in[1];
    const float* W2 = (const float*)d_in[2];
    float* out = (float*)d_out;

    static int smem_set = 0;
    if (!smem_set) {
        cudaFuncSetAttribute(k_gemm2, cudaFuncAttributeMaxDynamicSharedMemorySize,
                             2 * HID * 32 * (int)sizeof(float));
        smem_set = 1;
    }

    k_pool<<<3264, 256>>>(x, W1, W2);
    launch_pdl(k_gemm1,      dim3(KC, 7), dim3(256), 0, W1);
    launch_pdl(k_redrelu,    dim3(98),    dim3(256), (size_t)0);
    launch_pdl(k_gemm2,      dim3(98, 2), dim3(256), 2 * HID * 32 * sizeof(float), W2);
    launch_pdl(k_sel1,       dim3(32),    dim3(512), SEL_SMEM);
    launch_pdl(k_sel2_bcast1,dim3(424),   dim3(512), SEL_SMEM, out);
    launch_pdl(k_bcast2,     dim3(1568),  dim3(256), 0, out);
}

// round 15
// speedup vs baseline: 1.0270x; 1.0270x over previous
#include <cuda_runtime.h>
#include <cuda_bf16.h>
#include <math.h>

// Problem constants
#define B    64
#define C    256
#define S    3136          // 56*56
#define S4   784           // S/4 (float4 units)
#define HID  196
#define HID4 49            // HID/4
#define KSEL 1568          // rank of first KEPT element (0-indexed kth smallest)

// K-split for GEMM1
#define KC   49
#define KCH  64            // 3136/49

// Scratch (device globals: no allocation allowed)
__device__ float g_Yp[8][B * S];        // pooled partial sums (8 c-slices)
__device__ float g_Hpart[KC * B * HID]; // GEMM1 partials        [49][64*196]
__device__ float g_H[B * HID];          // relu(hidden)          [64,196]
__device__ float g_S[B * S];            // sigmoid outputs       [64,3136]
__device__ float g_M[B * S];            // masked row            [64,3136]
__device__ float g_scratch[128 * 8];    // prefetch sink (never read)

// ---------------------------------------------------------------------------
// K1: channel-mean pool (partial, c-split x8) FUSED with W1/W2 L2-prefetch.
// (proven R13 config)  grid 1696, block 256
// ---------------------------------------------------------------------------
__global__ void k_pool(const float* __restrict__ x,
                       const float* __restrict__ W1,
                       const float* __restrict__ W2) {
    int blk = blockIdx.x;
    if (blk < 128) {
        const int NF4 = (S * HID) / 4;               // 153664 float4 per matrix
        int t = blk * 256 + threadIdx.x;             // 0..32767
        float s = 0.f;
        const float4* w1 = reinterpret_cast<const float4*>(W1);
        const float4* w2 = reinterpret_cast<const float4*>(W2);
        for (int i = t; i < NF4; i += 128 * 256) {
            float4 a = __ldcg(w1 + i);
            float4 b4 = __ldcg(w2 + i);
            s += a.x + a.y + a.z + a.w + b4.x + b4.y + b4.z + b4.w;
        }
#pragma unroll
        for (int off = 16; off > 0; off >>= 1)
            s += __shfl_down_sync(0xFFFFFFFFu, s, off);
        if ((threadIdx.x & 31) == 0)
            g_scratch[blk * 8 + (threadIdx.x >> 5)] = s;
    } else {
        int id = (blk - 128) * 256 + threadIdx.x;    // 0..401407
        int q   = id / (B * S4);                     // c-slice 0..7
        int id2 = id - q * (B * S4);                 // 0..50175
        int b = id2 / S4;
        int f = id2 - b * S4;                        // float4 column index
        const float4* xp = reinterpret_cast<const float4*>(x)
                         + (size_t)b * C * S4 + (size_t)q * 32 * S4 + f;
        float sx = 0.f, sy = 0.f, sz = 0.f, sw = 0.f;
#pragma unroll 16
        for (int c = 0; c < 32; c++) {
            float4 v = __ldcs(xp + (size_t)c * S4);
            sx += v.x; sy += v.y; sz += v.z; sw += v.w;
        }
        float4 o; o.x = sx; o.y = sy; o.z = sz; o.w = sw;
        reinterpret_cast<float4*>(g_Yp[q])[(size_t)b * S4 + f] = o;
    }
}

// ---------------------------------------------------------------------------
// K2: GEMM1 partials, 2o x 4b register tile (proven R13 config) with PDL:
// W1 smem fill (independent) before cudaGridDependencySynchronize();
// g_Yp-dependent fill (8 partial slices) after.
// grid (49 kc, 7 o-tiles), block 256.
// ---------------------------------------------------------------------------
__global__ void k_gemm1(const float* __restrict__ W1) {
    __shared__ __align__(16) float sYT[KCH * 68];  // [j][b] (17.4KB)
    __shared__ __align__(8)  float sW[KCH * 28];   // [j][o_local] (7.2KB)
    int kc = blockIdx.x;
    int o0 = blockIdx.y * 28;
    int t = threadIdx.x;
    const float inv = 1.0f / 256.0f;

    // ---- independent preamble: W1 tile -> smem (overlaps pool tail) ----
    const float4* w4 = reinterpret_cast<const float4*>(W1);
    for (int idx = t; idx < 28 * 16; idx += 256) {
        int o = idx >> 4, jq = idx & 15;
        float4 w = w4[(size_t)(o0 + o) * S4 + kc * 16 + jq];
        sW[(jq * 4 + 0) * 28 + o] = w.x;
        sW[(jq * 4 + 1) * 28 + o] = w.y;
        sW[(jq * 4 + 2) * 28 + o] = w.z;
        sW[(jq * 4 + 3) * 28 + o] = w.w;
    }

    cudaGridDependencySynchronize();   // wait for k_pool's g_Yp writes

    for (int idx = t; idx < B * 16; idx += 256) {
        int b2 = idx >> 4, jq = idx & 15;
        int gi = b2 * S4 + kc * 16 + jq;
        float ax = 0.f, ay = 0.f, az = 0.f, aw = 0.f;
#pragma unroll
        for (int q = 0; q < 8; q++) {
            float4 v = reinterpret_cast<const float4*>(g_Yp[q])[gi];
            ax += v.x; ay += v.y; az += v.z; aw += v.w;
        }
        sYT[(jq * 4 + 0) * 68 + b2] = ax * inv;
        sYT[(jq * 4 + 1) * 68 + b2] = ay * inv;
        sYT[(jq * 4 + 2) * 68 + b2] = az * inv;
        sYT[(jq * 4 + 3) * 68 + b2] = aw * inv;
    }
    __syncthreads();

    if (t >= 224) return;
    int og = t % 14;                     // 2 o's: og*2, og*2+1
    int bg = t / 14;                     // 0..15 -> 4 b's: bg*4..+3
    float a00 = 0.f, a01 = 0.f, a02 = 0.f, a03 = 0.f;
    float a10 = 0.f, a11 = 0.f, a12 = 0.f, a13 = 0.f;
#pragma unroll 4
    for (int j = 0; j < KCH; j++) {
        float2 w = *reinterpret_cast<const float2*>(&sW[j * 28 + og * 2]);
        float4 y = *reinterpret_cast<const float4*>(&sYT[j * 68 + bg * 4]);
        a00 = fmaf(w.x, y.x, a00); a01 = fmaf(w.x, y.y, a01);
        a02 = fmaf(w.x, y.z, a02); a03 = fmaf(w.x, y.w, a03);
        a10 = fmaf(w.y, y.x, a10); a11 = fmaf(w.y, y.y, a11);
        a12 = fmaf(w.y, y.z, a12); a13 = fmaf(w.y, y.w, a13);
    }
    int ob = o0 + og * 2;
    int base = kc * (B * HID) + (bg * 4) * HID + ob;
    g_Hpart[base + 0 * HID + 0] = a00; g_Hpart[base + 0 * HID + 1] = a10;
    g_Hpart[base + 1 * HID + 0] = a01; g_Hpart[base + 1 * HID + 1] = a11;
    g_Hpart[base + 2 * HID + 0] = a02; g_Hpart[base + 2 * HID + 1] = a12;
    g_Hpart[base + 3 * HID + 0] = a03; g_Hpart[base + 3 * HID + 1] = a13;
}

// ---------------------------------------------------------------------------
// K3: reduce 49 partials + ReLU.  2 threads per output, shuffle combine.
// grid 98, block 256.  (proven)  PDL: sync at top.
// ---------------------------------------------------------------------------
__global__ void k_redrelu() {
    cudaGridDependencySynchronize();
    int tid = blockIdx.x * 256 + threadIdx.x;
    int g   = tid >> 1;                  // output index 0..12543
    int sub = tid & 1;
    float s = 0.f;
    for (int i = sub; i < KC; i += 2)
        s += g_Hpart[i * (B * HID) + g];
    s += __shfl_xor_sync(0xFFFFFFFFu, s, 1);
    if (sub == 0)
        g_H[g] = s > 0.f ? s : 0.f;
}

// ---------------------------------------------------------------------------
// K4: GEMM2 + sigmoid, 2n x 2b register tile (proven R13 config) with PDL:
// W2 fill (independent) before the dependency sync, g_H fill after.
// grid (98, 2), block 256, 50KB dynamic smem.
// ---------------------------------------------------------------------------
__global__ void k_gemm2(const float* __restrict__ W2) {
    extern __shared__ float dyn[];
    float* sW2 = dyn;                 // [j][n_local] pitch 32
    float* sHT = dyn + HID * 32;      // [j][b_local] pitch 32
    int n0 = blockIdx.x * 32;
    int b0 = blockIdx.y * 32;
    int t = threadIdx.x;

    // ---- independent preamble: W2 tile -> smem (overlaps redrelu) ----
    const float4* w4 = reinterpret_cast<const float4*>(W2);
    for (int idx = t; idx < 32 * HID4; idx += 256) {
        int nl = idx / HID4, jq = idx - nl * HID4;
        float4 w = w4[(size_t)(n0 + nl) * HID4 + jq];
        sW2[(jq * 4 + 0) * 32 + nl] = w.x;
        sW2[(jq * 4 + 1) * 32 + nl] = w.y;
        sW2[(jq * 4 + 2) * 32 + nl] = w.z;
        sW2[(jq * 4 + 3) * 32 + nl] = w.w;
    }

    cudaGridDependencySynchronize();   // wait for k_redrelu's g_H writes

    const float4* h4 = reinterpret_cast<const float4*>(g_H);
    for (int idx = t; idx < 32 * HID4; idx += 256) {
        int b2 = idx / HID4, jq = idx - b2 * HID4;
        float4 h = h4[(size_t)(b0 + b2) * HID4 + jq];
        sHT[(jq * 4 + 0) * 32 + b2] = h.x;
        sHT[(jq * 4 + 1) * 32 + b2] = h.y;
        sHT[(jq * 4 + 2) * 32 + b2] = h.z;
        sHT[(jq * 4 + 3) * 32 + b2] = h.w;
    }
    __syncthreads();

    int ng = t & 15;                             // 2 n's
    int bg = t >> 4;                             // 2 b's
    float a00 = 0.f, a01 = 0.f, a10 = 0.f, a11 = 0.f;
#pragma unroll 4
    for (int j = 0; j < HID; j++) {
        float2 w = *reinterpret_cast<const float2*>(&sW2[j * 32 + ng * 2]);
        float2 h = *reinterpret_cast<const float2*>(&sHT[j * 32 + bg * 2]);
        a00 = fmaf(h.x, w.x, a00); a01 = fmaf(h.x, w.y, a01);
        a10 = fmaf(h.y, w.x, a10); a11 = fmaf(h.y, w.y, a11);
    }
    int b = b0 + bg * 2;
    int n = n0 + ng * 2;
    g_S[(size_t)(b + 0) * S + n + 0] = 1.0f / (1.0f + expf(-a00));
    g_S[(size_t)(b + 0) * S + n + 1] = 1.0f / (1.0f + expf(-a01));
    g_S[(size_t)(b + 1) * S + n + 0] = 1.0f / (1.0f + expf(-a10));
    g_S[(size_t)(b + 1) * S + n + 1] = 1.0f / (1.0f + expf(-a11));
}

// ---------------------------------------------------------------------------
// K5: exact rank-1568 selection per row + masking (stable-argsort semantics).
// 4-pass radix, 512 threads (proven R13 config) with ONE delta: the 256-bin
// histogram is privatized into 2 copies (one per 256-thread half) to halve
// same-bin ATOMS serialization (sigmoid outputs cluster in few exponent
// bins).  PDL: sync at top.  grid 64, block 512.
// ---------------------------------------------------------------------------
__global__ void k_select() {
    __shared__ float sv[S];
    __shared__ unsigned int hist[2][256];
    __shared__ unsigned int wsum[16];
    __shared__ unsigned int sh_pref, sh_r;
    int b = blockIdx.x, t = threadIdx.x;       // t in 0..511
    int lane = t & 31, wid = t >> 5;           // 16 warps
    int half = t >> 8;                         // 0 or 1: private histogram copy

    cudaGridDependencySynchronize();           // wait for k_gemm2's g_S

    for (int i = t; i < S; i += 512) sv[i] = g_S[b * S + i];
    if (t == 0) { sh_pref = 0u; sh_r = KSEL; }
    __syncthreads();

    for (int shift = 24; shift >= 0; shift -= 8) {
        hist[0][t & 255] = 0u;                 // 512 threads zero both copies
        if (t < 256) hist[1][t] = 0u; else hist[1][t & 255] = 0u;
        __syncthreads();
        unsigned pref = sh_pref;
        unsigned r    = sh_r;
        unsigned hm   = (shift == 24) ? 0u : (0xFFFFFFFFu << (shift + 8));
        for (int i = t; i < S; i += 512) {
            unsigned u = __float_as_uint(sv[i]);
            if ((u & hm) == pref)
                atomicAdd(&hist[half][(u >> shift) & 255], 1u);
        }
        __syncthreads();
        unsigned v = (t < 256) ? (hist[0][t] + hist[1][t]) : 0u;
        unsigned x = v;
#pragma unroll
        for (int off = 1; off < 32; off <<= 1) {
            unsigned y = __shfl_up_sync(0xFFFFFFFFu, x, off);
            if (lane >= off) x += y;
        }
        if (lane == 31) wsum[wid] = x;
        __syncthreads();
        if (t < 16) {
            unsigned s = wsum[t];
#pragma unroll
            for (int off = 1; off < 16; off <<= 1) {
                unsigned y = __shfl_up_sync(0xFFFFu, s, off);
                if (t >= off) s += y;
            }
            wsum[t] = s;
        }
        __syncthreads();
        unsigned incl = x + (wid ? wsum[wid - 1] : 0u);
        unsigned excl = incl - v;
        if (v > 0u && r >= excl && r < incl) {   // exactly one thread (t<256)
            sh_pref = pref | ((unsigned)t << shift);
            sh_r    = r - excl;
        }
        __syncthreads();
    }
    unsigned T    = sh_pref;
    unsigned rfin = sh_r;

    int lo = (t * S) >> 9;
    int hi = ((t + 1) * S) >> 9;
    unsigned cnt = 0;
    for (int i = lo; i < hi; i++)
        cnt += (__float_as_uint(sv[i]) == T) ? 1u : 0u;
    unsigned x = cnt;
#pragma unroll
    for (int off = 1; off < 32; off <<= 1) {
        unsigned y = __shfl_up_sync(0xFFFFFFFFu, x, off);
        if (lane >= off) x += y;
    }
    if (lane == 31) wsum[wid] = x;
    __syncthreads();
    if (t < 16) {
        unsigned s = wsum[t];
#pragma unroll
        for (int off = 1; off < 16; off <<= 1) {
            unsigned y = __shfl_up_sync(0xFFFFu, s, off);
            if (t >= off) s += y;
        }
        wsum[t] = s;
    }
    __syncthreads();
    unsigned e = x - cnt + (wid ? wsum[wid - 1] : 0u);
    for (int i = lo; i < hi; i++) {
        unsigned u = __float_as_uint(sv[i]);
        float val = sv[i];
        if (u < T) val = 0.f;
        else if (u == T) { if (e < rfin) val = 0.f; e++; }
        g_M[b * S + i] = val;
    }
}

// ---------------------------------------------------------------------------
// K6: broadcast masked row over 256 planes.  grid 1568, block 256. (proven)
// PDL: sync at top.
// ---------------------------------------------------------------------------
__global__ void k_bcast(float* __restrict__ out) {
    cudaGridDependencySynchronize();           // wait for k_select's g_M
    int id = blockIdx.x * 256 + threadIdx.x;     // 0 .. 64*8*784-1
    int f  = id % S4;
    int bc = id / S4;                            // b*8 + cg
    int cg = bc & 7;
    int b  = bc >> 3;
    float4 v = __ldcg(reinterpret_cast<const float4*>(g_M) + (size_t)b * S4 + f);
    float4* op = reinterpret_cast<float4*>(out)
               + (size_t)(b * C + cg * 32) * S4 + f;
#pragma unroll 8
    for (int c = 0; c < 32; c++)
        __stcs(op + (size_t)c * S4, v);
}

// ---------------------------------------------------------------------------
// Helper: launch with programmatic stream serialization (PDL)
// ---------------------------------------------------------------------------
template <typename... Args>
static void launch_pdl(void (*kern)(Args...), dim3 grid, dim3 block,
                       size_t smem, Args... args) {
    cudaLaunchConfig_t cfg = {};
    cfg.gridDim = grid;
    cfg.blockDim = block;
    cfg.dynamicSmemBytes = smem;
    cfg.stream = 0;
    cudaLaunchAttribute attr[1];
    attr[0].id = cudaLaunchAttributeProgrammaticStreamSerialization;
    attr[0].val.programmaticStreamSerializationAllowed = 1;
    cfg.attrs = attr;
    cfg.numAttrs = 1;
    cudaLaunchKernelEx(&cfg, kern, args...);
}

// ---------------------------------------------------------------------------
extern "C" void kernel_launch(void* const* d_in, const int* in_sizes, int n_in,
                              void* d_out, int out_size) {
    const float* x  = (const float*)d_in[0];
    const float* W1 = (const float*)d_in[1];
    const float* W2 = (const float*)d_in[2];
    float* out = (float*)d_out;

    static int smem_set = 0;
    if (!smem_set) {
        cudaFuncSetAttribute(k_gemm2, cudaFuncAttributeMaxDynamicSharedMemorySize,
                             2 * HID * 32 * (int)sizeof(float));
        smem_set = 1;
    }

    k_pool<<<1696, 256>>>(x, W1, W2);
    launch_pdl(k_gemm1,   dim3(KC, 7), dim3(256), 0, W1);
    launch_pdl(k_redrelu, dim3(98),    dim3(256), (size_t)0);
    launch_pdl(k_gemm2,   dim3(98, 2), dim3(256), 2 * HID * 32 * sizeof(float), W2);
    launch_pdl(k_select,  dim3(B),     dim3(512), (size_t)0);
    launch_pdl(k_bcast,   dim3(1568),  dim3(256), 0, out);
}

// round 17
// speedup vs baseline: 1.0277x; 1.0006x over previous
#include <cuda_runtime.h>
#include <cuda_bf16.h>
#include <math.h>

// Problem constants
#define B    64
#define C    256
#define S    3136          // 56*56
#define S4   784           // S/4 (float4 units)
#define HID  196
#define HID4 49            // HID/4
#define KSEL 1568          // rank of first KEPT element (0-indexed kth smallest)

// K-split for GEMM1
#define KC   49
#define KCH  64            // 3136/49

// Scratch (device globals: no allocation allowed)
__device__ float g_Yp[8][B * S];        // pooled partial sums (8 c-slices)
__device__ float g_Hpart[KC * B * HID]; // GEMM1 partials        [49][64*196]
__device__ float g_H[B * HID];          // relu(hidden)          [64,196]
__device__ float g_S[B * S];            // sigmoid outputs       [64,3136]
__device__ float g_M[B * S];            // masked row            [64,3136]
__device__ float g_scratch[128 * 8];    // prefetch sink (never read)

// ---------------------------------------------------------------------------
// K1: channel-mean pool (partial, c-split x8) FUSED with W1/W2 L2-prefetch.
// Blocks 0..127:    warm W1+W2 (4.9MB) into L2 via __ldcg (wave-1 scheduled).
// Blocks 128..1695: 1568 balanced pool blocks; each thread sums one float4
//   column over 32 channels (__ldcs evict-first) into g_Yp[slice].
// grid 1696, block 256   (proven R13 config)
// ---------------------------------------------------------------------------
__global__ void k_pool(const float* __restrict__ x,
                       const float* __restrict__ W1,
                       const float* __restrict__ W2) {
    int blk = blockIdx.x;
    if (blk < 128) {
        const int NF4 = (S * HID) / 4;               // 153664 float4 per matrix
        int t = blk * 256 + threadIdx.x;             // 0..32767
        float s = 0.f;
        const float4* w1 = reinterpret_cast<const float4*>(W1);
        const float4* w2 = reinterpret_cast<const float4*>(W2);
        for (int i = t; i < NF4; i += 128 * 256) {
            float4 a = __ldcg(w1 + i);
            float4 b4 = __ldcg(w2 + i);
            s += a.x + a.y + a.z + a.w + b4.x + b4.y + b4.z + b4.w;
        }
#pragma unroll
        for (int off = 16; off > 0; off >>= 1)
            s += __shfl_down_sync(0xFFFFFFFFu, s, off);
        if ((threadIdx.x & 31) == 0)
            g_scratch[blk * 8 + (threadIdx.x >> 5)] = s;
    } else {
        int id = (blk - 128) * 256 + threadIdx.x;    // 0..401407
        int q   = id / (B * S4);                     // c-slice 0..7
        int id2 = id - q * (B * S4);                 // 0..50175
        int b = id2 / S4;
        int f = id2 - b * S4;                        // float4 column index
        const float4* xp = reinterpret_cast<const float4*>(x)
                         + (size_t)b * C * S4 + (size_t)q * 32 * S4 + f;
        float sx = 0.f, sy = 0.f, sz = 0.f, sw = 0.f;
#pragma unroll 16
        for (int c = 0; c < 32; c++) {
            float4 v = __ldcs(xp + (size_t)c * S4);
            sx += v.x; sy += v.y; sz += v.z; sw += v.w;
        }
        float4 o; o.x = sx; o.y = sy; o.z = sz; o.w = sw;
        reinterpret_cast<float4*>(g_Yp[q])[(size_t)b * S4 + f] = o;
    }
}

// ---------------------------------------------------------------------------
// K2: GEMM1 partials, 2o x 4b register tile (proven R9/R13 config) with PDL:
// W1 smem fill (independent) runs before cudaGridDependencySynchronize();
// the g_Yp-dependent fill (8 partial slices) runs after.
// grid (49 kc, 7 o-tiles), block 256.
// ---------------------------------------------------------------------------
__global__ void k_gemm1(const float* __restrict__ W1) {
    __shared__ __align__(16) float sYT[KCH * 68];  // [j][b] (17.4KB)
    __shared__ __align__(8)  float sW[KCH * 28];   // [j][o_local] (7.2KB)
    int kc = blockIdx.x;
    int o0 = blockIdx.y * 28;
    int t = threadIdx.x;
    const float inv = 1.0f / 256.0f;

    // ---- independent preamble: W1 tile -> smem (overlaps pool tail) ----
    const float4* w4 = reinterpret_cast<const float4*>(W1);
    for (int idx = t; idx < 28 * 16; idx += 256) {
        int o = idx >> 4, jq = idx & 15;
        float4 w = w4[(size_t)(o0 + o) * S4 + kc * 16 + jq];
        sW[(jq * 4 + 0) * 28 + o] = w.x;
        sW[(jq * 4 + 1) * 28 + o] = w.y;
        sW[(jq * 4 + 2) * 28 + o] = w.z;
        sW[(jq * 4 + 3) * 28 + o] = w.w;
    }

    cudaGridDependencySynchronize();   // wait for k_pool's g_Yp writes

    for (int idx = t; idx < B * 16; idx += 256) {
        int b2 = idx >> 4, jq = idx & 15;
        int gi = b2 * S4 + kc * 16 + jq;
        float ax = 0.f, ay = 0.f, az = 0.f, aw = 0.f;
#pragma unroll
        for (int q = 0; q < 8; q++) {
            float4 v = reinterpret_cast<const float4*>(g_Yp[q])[gi];
            ax += v.x; ay += v.y; az += v.z; aw += v.w;
        }
        sYT[(jq * 4 + 0) * 68 + b2] = ax * inv;
        sYT[(jq * 4 + 1) * 68 + b2] = ay * inv;
        sYT[(jq * 4 + 2) * 68 + b2] = az * inv;
        sYT[(jq * 4 + 3) * 68 + b2] = aw * inv;
    }
    __syncthreads();

    if (t >= 224) return;
    int og = t % 14;                     // 2 o's: og*2, og*2+1
    int bg = t / 14;                     // 0..15 -> 4 b's: bg*4..+3
    float a00 = 0.f, a01 = 0.f, a02 = 0.f, a03 = 0.f;
    float a10 = 0.f, a11 = 0.f, a12 = 0.f, a13 = 0.f;
#pragma unroll 4
    for (int j = 0; j < KCH; j++) {
        float2 w = *reinterpret_cast<const float2*>(&sW[j * 28 + og * 2]);
        float4 y = *reinterpret_cast<const float4*>(&sYT[j * 68 + bg * 4]);
        a00 = fmaf(w.x, y.x, a00); a01 = fmaf(w.x, y.y, a01);
        a02 = fmaf(w.x, y.z, a02); a03 = fmaf(w.x, y.w, a03);
        a10 = fmaf(w.y, y.x, a10); a11 = fmaf(w.y, y.y, a11);
        a12 = fmaf(w.y, y.z, a12); a13 = fmaf(w.y, y.w, a13);
    }
    int ob = o0 + og * 2;
    int base = kc * (B * HID) + (bg * 4) * HID + ob;
    g_Hpart[base + 0 * HID + 0] = a00; g_Hpart[base + 0 * HID + 1] = a10;
    g_Hpart[base + 1 * HID + 0] = a01; g_Hpart[base + 1 * HID + 1] = a11;
    g_Hpart[base + 2 * HID + 0] = a02; g_Hpart[base + 2 * HID + 1] = a12;
    g_Hpart[base + 3 * HID + 0] = a03; g_Hpart[base + 3 * HID + 1] = a13;
}

// ---------------------------------------------------------------------------
// K3: reduce 49 partials + ReLU.  2 threads per output, shuffle combine.
// grid 98, block 256.  (proven)  PDL: sync at top.
// ---------------------------------------------------------------------------
__global__ void k_redrelu() {
    cudaGridDependencySynchronize();
    int tid = blockIdx.x * 256 + threadIdx.x;
    int g   = tid >> 1;                  // output index 0..12543
    int sub = tid & 1;
    float s = 0.f;
    for (int i = sub; i < KC; i += 2)
        s += g_Hpart[i * (B * HID) + g];
    s += __shfl_xor_sync(0xFFFFFFFFu, s, 1);
    if (sub == 0)
        g_H[g] = s > 0.f ? s : 0.f;
}

// ---------------------------------------------------------------------------
// K4: GEMM2 + sigmoid, 2n x 2b register tile (proven R9/R13 config) with PDL:
// W2 fill (independent) before the dependency sync, g_H fill after.
// grid (98, 2), block 256, 50KB dynamic smem.
// ---------------------------------------------------------------------------
__global__ void k_gemm2(const float* __restrict__ W2) {
    extern __shared__ float dyn[];
    float* sW2 = dyn;                 // [j][n_local] pitch 32
    float* sHT = dyn + HID * 32;      // [j][b_local] pitch 32
    int n0 = blockIdx.x * 32;
    int b0 = blockIdx.y * 32;
    int t = threadIdx.x;

    // ---- independent preamble: W2 tile -> smem (overlaps redrelu) ----
    const float4* w4 = reinterpret_cast<const float4*>(W2);
    for (int idx = t; idx < 32 * HID4; idx += 256) {
        int nl = idx / HID4, jq = idx - nl * HID4;
        float4 w = w4[(size_t)(n0 + nl) * HID4 + jq];
        sW2[(jq * 4 + 0) * 32 + nl] = w.x;
        sW2[(jq * 4 + 1) * 32 + nl] = w.y;
        sW2[(jq * 4 + 2) * 32 + nl] = w.z;
        sW2[(jq * 4 + 3) * 32 + nl] = w.w;
    }

    cudaGridDependencySynchronize();   // wait for k_redrelu's g_H writes

    const float4* h4 = reinterpret_cast<const float4*>(g_H);
    for (int idx = t; idx < 32 * HID4; idx += 256) {
        int b2 = idx / HID4, jq = idx - b2 * HID4;
        float4 h = h4[(size_t)(b0 + b2) * HID4 + jq];
        sHT[(jq * 4 + 0) * 32 + b2] = h.x;
        sHT[(jq * 4 + 1) * 32 + b2] = h.y;
        sHT[(jq * 4 + 2) * 32 + b2] = h.z;
        sHT[(jq * 4 + 3) * 32 + b2] = h.w;
    }
    __syncthreads();

    int ng = t & 15;                             // 2 n's
    int bg = t >> 4;                             // 2 b's
    float a00 = 0.f, a01 = 0.f, a10 = 0.f, a11 = 0.f;
#pragma unroll 4
    for (int j = 0; j < HID; j++) {
        float2 w = *reinterpret_cast<const float2*>(&sW2[j * 32 + ng * 2]);
        float2 h = *reinterpret_cast<const float2*>(&sHT[j * 32 + bg * 2]);
        a00 = fmaf(h.x, w.x, a00); a01 = fmaf(h.x, w.y, a01);
        a10 = fmaf(h.y, w.x, a10); a11 = fmaf(h.y, w.y, a11);
    }
    int b = b0 + bg * 2;
    int n = n0 + ng * 2;
    g_S[(size_t)(b + 0) * S + n + 0] = 1.0f / (1.0f + expf(-a00));
    g_S[(size_t)(b + 0) * S + n + 1] = 1.0f / (1.0f + expf(-a01));
    g_S[(size_t)(b + 1) * S + n + 0] = 1.0f / (1.0f + expf(-a10));
    g_S[(size_t)(b + 1) * S + n + 1] = 1.0f / (1.0f + expf(-a11));
}

// ---------------------------------------------------------------------------
// K5: exact rank-1568 selection per row + masking (stable-argsort semantics).
// 4-pass radix, 512 threads (proven R8/R13 config).  PDL: sync at top.
// grid 64, block 512.
// ---------------------------------------------------------------------------
__global__ void k_select() {
    __shared__ float sv[S];
    __shared__ unsigned int hist[256];
    __shared__ unsigned int wsum[16];
    __shared__ unsigned int sh_pref, sh_r;
    int b = blockIdx.x, t = threadIdx.x;       // t in 0..511
    int lane = t & 31, wid = t >> 5;           // 16 warps

    cudaGridDependencySynchronize();           // wait for k_gemm2's g_S

    for (int i = t; i < S; i += 512) sv[i] = g_S[b * S + i];
    if (t == 0) { sh_pref = 0u; sh_r = KSEL; }
    __syncthreads();

    for (int shift = 24; shift >= 0; shift -= 8) {
        if (t < 256) hist[t] = 0u;
        __syncthreads();
        unsigned pref = sh_pref;
        unsigned r    = sh_r;
        unsigned hm   = (shift == 24) ? 0u : (0xFFFFFFFFu << (shift + 8));
        for (int i = t; i < S; i += 512) {
            unsigned u = __float_as_uint(sv[i]);
            if ((u & hm) == pref) atomicAdd(&hist[(u >> shift) & 255], 1u);
        }
        __syncthreads();
        unsigned v = (t < 256) ? hist[t] : 0u;
        unsigned x = v;
#pragma unroll
        for (int off = 1; off < 32; off <<= 1) {
            unsigned y = __shfl_up_sync(0xFFFFFFFFu, x, off);
            if (lane >= off) x += y;
        }
        if (lane == 31) wsum[wid] = x;
        __syncthreads();
        if (t < 16) {
            unsigned s = wsum[t];
#pragma unroll
            for (int off = 1; off < 16; off <<= 1) {
                unsigned y = __shfl_up_sync(0xFFFFu, s, off);
                if (t >= off) s += y;
            }
            wsum[t] = s;
        }
        __syncthreads();
        unsigned incl = x + (wid ? wsum[wid - 1] : 0u);
        unsigned excl = incl - v;
        if (v > 0u && r >= excl && r < incl) {   // exactly one thread (t<256)
            sh_pref = pref | ((unsigned)t << shift);
            sh_r    = r - excl;
        }
        __syncthreads();
    }
    unsigned T    = sh_pref;
    unsigned rfin = sh_r;

    int lo = (t * S) >> 9;
    int hi = ((t + 1) * S) >> 9;
    unsigned cnt = 0;
    for (int i = lo; i < hi; i++)
        cnt += (__float_as_uint(sv[i]) == T) ? 1u : 0u;
    unsigned x = cnt;
#pragma unroll
    for (int off = 1; off < 32; off <<= 1) {
        unsigned y = __shfl_up_sync(0xFFFFFFFFu, x, off);
        if (lane >= off) x += y;
    }
    if (lane == 31) wsum[wid] = x;
    __syncthreads();
    if (t < 16) {
        unsigned s = wsum[t];
#pragma unroll
        for (int off = 1; off < 16; off <<= 1) {
            unsigned y = __shfl_up_sync(0xFFFFu, s, off);
            if (t >= off) s += y;
        }
        wsum[t] = s;
    }
    __syncthreads();
    unsigned e = x - cnt + (wid ? wsum[wid - 1] : 0u);
    for (int i = lo; i < hi; i++) {
        unsigned u = __float_as_uint(sv[i]);
        float val = sv[i];
        if (u < T) val = 0.f;
        else if (u == T) { if (e < rfin) val = 0.f; e++; }
        g_M[b * S + i] = val;
    }
}

// ---------------------------------------------------------------------------
// K6: broadcast masked row over 256 planes.  grid 1568, block 256. (proven)
// PDL: sync at top (gains launch-ramp overlap with k_select).
// ---------------------------------------------------------------------------
__global__ void k_bcast(float* __restrict__ out) {
    cudaGridDependencySynchronize();           // wait for k_select's g_M
    int id = blockIdx.x * 256 + threadIdx.x;     // 0 .. 64*8*784-1
    int f  = id % S4;
    int bc = id / S4;                            // b*8 + cg
    int cg = bc & 7;
    int b  = bc >> 3;
    float4 v = __ldcg(reinterpret_cast<const float4*>(g_M) + (size_t)b * S4 + f);
    float4* op = reinterpret_cast<float4*>(out)
               + (size_t)(b * C + cg * 32) * S4 + f;
#pragma unroll 8
    for (int c = 0; c < 32; c++)
        __stcs(op + (size_t)c * S4, v);
}

// ---------------------------------------------------------------------------
// Helper: launch with programmatic stream serialization (PDL)
// ---------------------------------------------------------------------------
template <typename... Args>
static void launch_pdl(void (*kern)(Args...), dim3 grid, dim3 block,
                       size_t smem, Args... args) {
    cudaLaunchConfig_t cfg = {};
    cfg.gridDim = grid;
    cfg.blockDim = block;
    cfg.dynamicSmemBytes = smem;
    cfg.stream = 0;
    cudaLaunchAttribute attr[1];
    attr[0].id = cudaLaunchAttributeProgrammaticStreamSerialization;
    attr[0].val.programmaticStreamSerializationAllowed = 1;
    cfg.attrs = attr;
    cfg.numAttrs = 1;
    cudaLaunchKernelEx(&cfg, kern, args...);
}

// ---------------------------------------------------------------------------
extern "C" void kernel_launch(void* const* d_in, const int* in_sizes, int n_in,
                              void* d_out, int out_size) {
    const float* x  = (const float*)d_in[0];
    const float* W1 = (const float*)d_in[1];
    const float* W2 = (const float*)d_in[2];
    float* out = (float*)d_out;

    static int smem_set = 0;
    if (!smem_set) {
        cudaFuncSetAttribute(k_gemm2, cudaFuncAttributeMaxDynamicSharedMemorySize,
                             2 * HID * 32 * (int)sizeof(float));
        smem_set = 1;
    }

    k_pool<<<1696, 256>>>(x, W1, W2);
    launch_pdl(k_gemm1,   dim3(KC, 7), dim3(256), 0, W1);
    launch_pdl(k_redrelu, dim3(98),    dim3(256), (size_t)0);
    launch_pdl(k_gemm2,   dim3(98, 2), dim3(256), 2 * HID * 32 * sizeof(float), W2);
    launch_pdl(k_select,  dim3(B),     dim3(512), (size_t)0);
    launch_pdl(k_bcast,   dim3(1568),  dim3(256), 0, out);
}